// round 6
// baseline (speedup 1.0000x reference)
#include <cuda_runtime.h>
#include <math.h>

#define FEAT    128
#define N_RELS  8
#define MAX_NODES 100000

// Scratch (allocation-free rule: __device__ globals).
// h_all layout [node][rel][feat] so each edge gathers one contiguous 512B row.
__device__ float g_h_all[(size_t)MAX_NODES * N_RELS * FEAT];   // 409.6 MB
__device__ float g_gate [(size_t)MAX_NODES * N_RELS];          // 3.2 MB

// ---------------------------------------------------------------------------
// GEMM: h_all[m][r][f] = sum_d h[m][d] * W[r][d][f]
// 128x128 block tile, BK=8, 256 threads, 8x8 microtile (4+4 split layout for
// conflict-free LDS128).
// ---------------------------------------------------------------------------
__global__ __launch_bounds__(256) void rgcn_gemm(const float* __restrict__ h,
                                                 const float* __restrict__ W,
                                                 int n_nodes)
{
    const int r     = blockIdx.y;
    const int mBase = blockIdx.x * 128;
    const float* B  = W + (size_t)r * FEAT * FEAT;   // [128][128] row-major (d, f)

    __shared__ float As[8][128];   // [k][m]
    __shared__ float Bs[8][128];   // [k][n]

    const int tid  = threadIdx.x;
    const int trow = tid >> 4;          // 0..15
    const int tcol = tid & 15;          // 0..15

    // global->shared load mapping
    const int aRow = tid >> 1;          // 0..127 (node row within tile)
    const int aCol = (tid & 1) * 4;     // 0 or 4 (k offset)
    const int bRow = tid >> 5;          // 0..7   (k row)
    const int bCol = (tid & 31) * 4;    // 0..124 (f col)

    const int  m_a    = mBase + aRow;
    const bool aValid = (m_a < n_nodes);
    const float* aPtr = h + (size_t)m_a * FEAT + aCol;

    float acc[8][8];
#pragma unroll
    for (int i = 0; i < 8; i++)
#pragma unroll
        for (int j = 0; j < 8; j++) acc[i][j] = 0.0f;

    for (int k0 = 0; k0 < FEAT; k0 += 8) {
        float4 av = make_float4(0.f, 0.f, 0.f, 0.f);
        if (aValid) av = *(const float4*)(aPtr + k0);
        As[aCol + 0][aRow] = av.x;
        As[aCol + 1][aRow] = av.y;
        As[aCol + 2][aRow] = av.z;
        As[aCol + 3][aRow] = av.w;
        *(float4*)&Bs[bRow][bCol] = *(const float4*)(B + (size_t)(k0 + bRow) * FEAT + bCol);
        __syncthreads();

#pragma unroll
        for (int kk = 0; kk < 8; kk++) {
            float ra[8], rb[8];
            *(float4*)&ra[0] = *(const float4*)&As[kk][trow * 4];
            *(float4*)&ra[4] = *(const float4*)&As[kk][trow * 4 + 64];
            *(float4*)&rb[0] = *(const float4*)&Bs[kk][tcol * 4];
            *(float4*)&rb[4] = *(const float4*)&Bs[kk][tcol * 4 + 64];
#pragma unroll
            for (int i = 0; i < 8; i++)
#pragma unroll
                for (int j = 0; j < 8; j++)
                    acc[i][j] = fmaf(ra[i], rb[j], acc[i][j]);
        }
        __syncthreads();
    }

    // store: rows {mBase + g*64 + trow*4 + i}, cols {tcol*4 (+64)}
#pragma unroll
    for (int g = 0; g < 2; g++) {
#pragma unroll
        for (int i = 0; i < 4; i++) {
            int m = mBase + g * 64 + trow * 4 + i;
            if (m < n_nodes) {
                float* dstp = g_h_all + ((size_t)m * N_RELS + r) * FEAT;
                float4 v0 = make_float4(acc[g*4+i][0], acc[g*4+i][1], acc[g*4+i][2], acc[g*4+i][3]);
                float4 v1 = make_float4(acc[g*4+i][4], acc[g*4+i][5], acc[g*4+i][6], acc[g*4+i][7]);
                *(float4*)(dstp + tcol * 4)      = v0;
                *(float4*)(dstp + tcol * 4 + 64) = v1;
            }
        }
    }
}

// ---------------------------------------------------------------------------
// Gate GEMV: g_gate[n][r] = sum_d h[n][d] * gw[r][d]   (warp per node)
// ---------------------------------------------------------------------------
__global__ __launch_bounds__(256) void rgcn_gate(const float* __restrict__ h,
                                                 const float* __restrict__ gw,
                                                 int n_nodes)
{
    __shared__ float sgw[N_RELS][FEAT];
    for (int i = threadIdx.x; i < N_RELS * FEAT; i += blockDim.x)
        sgw[i / FEAT][i % FEAT] = gw[i];
    __syncthreads();

    int warp = (blockIdx.x * blockDim.x + threadIdx.x) >> 5;
    int lane = threadIdx.x & 31;
    if (warp >= n_nodes) return;

    float4 hv = *(const float4*)(h + (size_t)warp * FEAT + lane * 4);
#pragma unroll
    for (int r = 0; r < N_RELS; r++) {
        float4 wv = *(const float4*)&sgw[r][lane * 4];
        float d = hv.x * wv.x + hv.y * wv.y + hv.z * wv.z + hv.w * wv.w;
#pragma unroll
        for (int off = 16; off; off >>= 1)
            d += __shfl_xor_sync(0xffffffffu, d, off);
        if (lane == 0) g_gate[(size_t)warp * N_RELS + r] = d;
    }
}

// ---------------------------------------------------------------------------
// Edge kernel: warp per edge. Gather one 512B h_all row, scale by
// norm * sigmoid(gate), scatter-add into out[dst].
// ---------------------------------------------------------------------------
__global__ __launch_bounds__(256) void rgcn_edge(const int* __restrict__ src,
                                                 const int* __restrict__ dst,
                                                 const int* __restrict__ rel,
                                                 const float* __restrict__ norm,
                                                 float* __restrict__ out,
                                                 int n_edges)
{
    int warp = (blockIdx.x * blockDim.x + threadIdx.x) >> 5;
    int lane = threadIdx.x & 31;
    if (warp >= n_edges) return;

    int s = src[warp];
    int d = dst[warp];
    int r = rel[warp];

    float gv    = g_gate[(size_t)s * N_RELS + r];
    float scale = norm[warp] / (1.0f + __expf(-gv));

    const float4* hp = (const float4*)(g_h_all + ((size_t)s * N_RELS + r) * FEAT);
    float4 v = hp[lane];

    float* o = out + (size_t)d * FEAT + lane * 4;
    atomicAdd(o + 0, v.x * scale);
    atomicAdd(o + 1, v.y * scale);
    atomicAdd(o + 2, v.z * scale);
    atomicAdd(o + 3, v.w * scale);
}

// ---------------------------------------------------------------------------
// In-place ReLU over out (float4 granularity)
// ---------------------------------------------------------------------------
__global__ void rgcn_relu(float4* out, int n4)
{
    int i = blockIdx.x * blockDim.x + threadIdx.x;
    if (i < n4) {
        float4 v = out[i];
        v.x = fmaxf(v.x, 0.f);
        v.y = fmaxf(v.y, 0.f);
        v.z = fmaxf(v.z, 0.f);
        v.w = fmaxf(v.w, 0.f);
        out[i] = v;
    }
}

extern "C" void kernel_launch(void* const* d_in, const int* in_sizes, int n_in,
                              void* d_out, int out_size)
{
    const float* h    = (const float*)d_in[0];   // [N,128]
    const float* W    = (const float*)d_in[1];   // [8,128,128]
    const float* gw   = (const float*)d_in[2];   // [8,128,1]
    const float* norm = (const float*)d_in[3];   // [E,1]
    const int*   src  = (const int*)  d_in[4];   // [E]
    const int*   dst  = (const int*)  d_in[5];   // [E]
    const int*   rel  = (const int*)  d_in[6];   // [E]
    float* out = (float*)d_out;                  // [N,128] fp32

    const int n_nodes = in_sizes[0] / FEAT;
    const int n_edges = in_sizes[4];

    // zero accumulator (d_out is poisoned)
    cudaMemsetAsync(out, 0, (size_t)out_size * sizeof(float));

    dim3 ggrid((n_nodes + 127) / 128, N_RELS);
    rgcn_gemm<<<ggrid, 256>>>(h, W, n_nodes);

    rgcn_gate<<<((size_t)n_nodes * 32 + 255) / 256, 256>>>(h, gw, n_nodes);

    rgcn_edge<<<((size_t)n_edges * 32 + 255) / 256, 256>>>(src, dst, rel, norm, out, n_edges);

    int n4 = out_size / 4;
    rgcn_relu<<<(n4 + 255) / 256, 256>>>((float4*)out, n4);
}

// round 12
// speedup vs baseline: 1.5117x; 1.5117x over previous
#include <cuda_runtime.h>
#include <cuda_bf16.h>
#include <math.h>
#include <stdint.h>

#define FEAT      128
#define N_RELS    8
#define MAX_NODES 100000
#define BK        32
#define ASTRIDE   40            // bf16 elems per smem row (32 + 8 pad -> 80B)

// ---------------------------------------------------------------------------
// Scratch (__device__ globals: allocation-free rule)
// ---------------------------------------------------------------------------
__device__ float g_h_all[(size_t)MAX_NODES * N_RELS * FEAT];  // [n][r][f]
__device__ float g_gate [(size_t)MAX_NODES * N_RELS];
__device__ __align__(16) __nv_bfloat16 g_WT_hi[N_RELS * FEAT * FEAT]; // [r][f][d]
__device__ __align__(16) __nv_bfloat16 g_WT_lo[N_RELS * FEAT * FEAT];

// mma.sync bf16 (legal on plain sm_103 target; no tcgen05 anywhere)
#define MMA_BF16(d, a, b) \
    asm volatile("mma.sync.aligned.m16n8k16.row.col.f32.bf16.bf16.f32 " \
        "{%0,%1,%2,%3}, {%4,%5,%6,%7}, {%8,%9}, {%0,%1,%2,%3};" \
        : "+f"((d)[0]), "+f"((d)[1]), "+f"((d)[2]), "+f"((d)[3]) \
        : "r"((a)[0]), "r"((a)[1]), "r"((a)[2]), "r"((a)[3]), \
          "r"((b)[0]), "r"((b)[1]))

// ---------------------------------------------------------------------------
// W prep: transpose + bf16 hi/lo split.  out[r][f][d] from W[r][d][f]
// ---------------------------------------------------------------------------
__global__ void rgcn_wprep(const float* __restrict__ W) {
    int idx = blockIdx.x * blockDim.x + threadIdx.x;
    if (idx >= N_RELS * FEAT * FEAT) return;
    int d = idx & 127, f = (idx >> 7) & 127, r = idx >> 14;
    float w = W[((size_t)r * FEAT + d) * FEAT + f];
    __nv_bfloat16 hi = __float2bfloat16(w);
    float lo = w - __bfloat162float(hi);
    g_WT_hi[idx] = hi;
    g_WT_lo[idx] = __float2bfloat16(lo);
}

// ---------------------------------------------------------------------------
// Tensor GEMM (3xBF16): h_all[m][r][f] = h[m][:] @ W[r][:][f]
// CTA: 128 nodes x 128 feats for one rel. 256 thr = 8 warps (4m x 2n),
// warp tile 32x64, mma m16n8k16, K chunked by 32.
// ---------------------------------------------------------------------------
__global__ __launch_bounds__(256) void rgcn_gemm_mma(const float* __restrict__ h,
                                                     const __nv_bfloat16* __restrict__ WThi,
                                                     const __nv_bfloat16* __restrict__ WTlo,
                                                     int n_nodes)
{
    __shared__ __align__(16) __nv_bfloat16 sAhi[128 * ASTRIDE];
    __shared__ __align__(16) __nv_bfloat16 sAlo[128 * ASTRIDE];
    __shared__ __align__(16) __nv_bfloat16 sBhi[128 * ASTRIDE];
    __shared__ __align__(16) __nv_bfloat16 sBlo[128 * ASTRIDE];

    const int tid  = threadIdx.x;
    const int lane = tid & 31;
    const int warp = tid >> 5;
    const int wm   = (warp & 3) * 32;   // warp m offset (4 warps along M)
    const int wn   = (warp >> 2) * 64;  // warp n offset (2 warps along N)
    const int g    = lane >> 2;         // 0..7
    const int tg   = lane & 3;          // 0..3

    const int r     = blockIdx.x;       // rel fast -> 8 CTAs share A via L2
    const int mBase = blockIdx.y * 128;

    const int ldRow = tid >> 2;         // 0..63
    const int ldCol = (tid & 3) * 8;    // 0,8,16,24

    float acc[2][8][4] = {};

    for (int c = 0; c < 4; c++) {
        // ---- gmem fetch (overlaps previous chunk's MMAs) ----
        float4 av[2][2];
        uint4  bh[2], bl[2];
#pragma unroll
        for (int half = 0; half < 2; half++) {
            const int row = half * 64 + ldRow;
            const int m   = mBase + row;
            av[half][0] = make_float4(0.f, 0.f, 0.f, 0.f);
            av[half][1] = make_float4(0.f, 0.f, 0.f, 0.f);
            if (m < n_nodes) {
                const float* p = h + (size_t)m * FEAT + c * BK + ldCol;
                av[half][0] = *(const float4*)p;
                av[half][1] = *(const float4*)(p + 4);
            }
            const size_t bi = ((size_t)(r * 128 + row)) * 128 + c * BK + ldCol;
            bh[half] = *(const uint4*)(WThi + bi);
            bl[half] = *(const uint4*)(WTlo + bi);
        }

        __syncthreads();   // previous chunk's fragment reads are done

        // ---- split + stage into smem ----
#pragma unroll
        for (int half = 0; half < 2; half++) {
            const int row = half * 64 + ldRow;
            __nv_bfloat16 hi8[8], lo8[8];
            const float* fv = (const float*)&av[half][0];
#pragma unroll
            for (int i = 0; i < 8; i++) {
                float x = fv[i];
                __nv_bfloat16 hb = __float2bfloat16(x);
                hi8[i] = hb;
                lo8[i] = __float2bfloat16(x - __bfloat162float(hb));
            }
            *(uint4*)&sAhi[row * ASTRIDE + ldCol] = *(const uint4*)hi8;
            *(uint4*)&sAlo[row * ASTRIDE + ldCol] = *(const uint4*)lo8;
            *(uint4*)&sBhi[row * ASTRIDE + ldCol] = bh[half];
            *(uint4*)&sBlo[row * ASTRIDE + ldCol] = bl[half];
        }
        __syncthreads();

        // ---- MMA: 2 ksteps x 3 split-terms x (2m x 8n) ----
#pragma unroll
        for (int ks = 0; ks < 2; ks++) {
            const int kk = ks * 16 + tg * 2;
            uint32_t ahi[2][4], alo[2][4], bhi[8][2], blo[8][2];
#pragma unroll
            for (int mt = 0; mt < 2; mt++) {
                const int mr = wm + mt * 16 + g;
                ahi[mt][0] = *(const uint32_t*)&sAhi[mr * ASTRIDE + kk];
                ahi[mt][1] = *(const uint32_t*)&sAhi[(mr + 8) * ASTRIDE + kk];
                ahi[mt][2] = *(const uint32_t*)&sAhi[mr * ASTRIDE + kk + 8];
                ahi[mt][3] = *(const uint32_t*)&sAhi[(mr + 8) * ASTRIDE + kk + 8];
                alo[mt][0] = *(const uint32_t*)&sAlo[mr * ASTRIDE + kk];
                alo[mt][1] = *(const uint32_t*)&sAlo[(mr + 8) * ASTRIDE + kk];
                alo[mt][2] = *(const uint32_t*)&sAlo[mr * ASTRIDE + kk + 8];
                alo[mt][3] = *(const uint32_t*)&sAlo[(mr + 8) * ASTRIDE + kk + 8];
            }
#pragma unroll
            for (int nt = 0; nt < 8; nt++) {
                const int nr = wn + nt * 8 + g;
                bhi[nt][0] = *(const uint32_t*)&sBhi[nr * ASTRIDE + kk];
                bhi[nt][1] = *(const uint32_t*)&sBhi[nr * ASTRIDE + kk + 8];
                blo[nt][0] = *(const uint32_t*)&sBlo[nr * ASTRIDE + kk];
                blo[nt][1] = *(const uint32_t*)&sBlo[nr * ASTRIDE + kk + 8];
            }
#pragma unroll
            for (int mt = 0; mt < 2; mt++)
#pragma unroll
                for (int nt = 0; nt < 8; nt++) {
                    MMA_BF16(acc[mt][nt], ahi[mt], bhi[nt]);
                    MMA_BF16(acc[mt][nt], ahi[mt], blo[nt]);
                    MMA_BF16(acc[mt][nt], alo[mt], bhi[nt]);
                }
        }
    }

    // ---- epilogue: c-frag rows (g, g+8), cols tg*2..+1 per n-tile ----
#pragma unroll
    for (int mt = 0; mt < 2; mt++) {
#pragma unroll
        for (int ro = 0; ro < 2; ro++) {
            const int m = mBase + wm + mt * 16 + g + ro * 8;
            if (m < n_nodes) {
                float* dstp = g_h_all + ((size_t)m * N_RELS + r) * FEAT;
#pragma unroll
                for (int nt = 0; nt < 8; nt++) {
                    float2 v;
                    v.x = acc[mt][nt][ro * 2 + 0];
                    v.y = acc[mt][nt][ro * 2 + 1];
                    *(float2*)(dstp + wn + nt * 8 + tg * 2) = v;
                }
            }
        }
    }
}

// ---------------------------------------------------------------------------
// Gate GEMV (warp per node)
// ---------------------------------------------------------------------------
__global__ __launch_bounds__(256) void rgcn_gate(const float* __restrict__ h,
                                                 const float* __restrict__ gw,
                                                 int n_nodes)
{
    __shared__ float sgw[N_RELS][FEAT];
    for (int i = threadIdx.x; i < N_RELS * FEAT; i += blockDim.x)
        sgw[i / FEAT][i % FEAT] = gw[i];
    __syncthreads();

    int warp = (blockIdx.x * blockDim.x + threadIdx.x) >> 5;
    int lane = threadIdx.x & 31;
    if (warp >= n_nodes) return;

    float4 hv = *(const float4*)(h + (size_t)warp * FEAT + lane * 4);
#pragma unroll
    for (int r = 0; r < N_RELS; r++) {
        float4 wv = *(const float4*)&sgw[r][lane * 4];
        float d = hv.x * wv.x + hv.y * wv.y + hv.z * wv.z + hv.w * wv.w;
#pragma unroll
        for (int off = 16; off; off >>= 1)
            d += __shfl_xor_sync(0xffffffffu, d, off);
        if (lane == 0) g_gate[(size_t)warp * N_RELS + r] = d;
    }
}

// ---------------------------------------------------------------------------
// Edge gather/scatter (warp per edge)
// ---------------------------------------------------------------------------
__global__ __launch_bounds__(256) void rgcn_edge(const int* __restrict__ src,
                                                 const int* __restrict__ dst,
                                                 const int* __restrict__ rel,
                                                 const float* __restrict__ norm,
                                                 float* __restrict__ out,
                                                 int n_edges)
{
    int warp = (blockIdx.x * blockDim.x + threadIdx.x) >> 5;
    int lane = threadIdx.x & 31;
    if (warp >= n_edges) return;

    int s = src[warp], d = dst[warp], r = rel[warp];
    float gv    = g_gate[(size_t)s * N_RELS + r];
    float scale = norm[warp] / (1.0f + __expf(-gv));

    const float4* hp = (const float4*)(g_h_all + ((size_t)s * N_RELS + r) * FEAT);
    float4 v = hp[lane];

    float* o = out + (size_t)d * FEAT + lane * 4;
    atomicAdd(o + 0, v.x * scale);
    atomicAdd(o + 1, v.y * scale);
    atomicAdd(o + 2, v.z * scale);
    atomicAdd(o + 3, v.w * scale);
}

__global__ void rgcn_relu(float4* out, int n4)
{
    int i = blockIdx.x * blockDim.x + threadIdx.x;
    if (i < n4) {
        float4 v = out[i];
        v.x = fmaxf(v.x, 0.f); v.y = fmaxf(v.y, 0.f);
        v.z = fmaxf(v.z, 0.f); v.w = fmaxf(v.w, 0.f);
        out[i] = v;
    }
}

extern "C" void kernel_launch(void* const* d_in, const int* in_sizes, int n_in,
                              void* d_out, int out_size)
{
    const float* h    = (const float*)d_in[0];
    const float* W    = (const float*)d_in[1];
    const float* gw   = (const float*)d_in[2];
    const float* norm = (const float*)d_in[3];
    const int*   src  = (const int*)  d_in[4];
    const int*   dst  = (const int*)  d_in[5];
    const int*   rel  = (const int*)  d_in[6];
    float* out = (float*)d_out;

    const int n_nodes = in_sizes[0] / FEAT;
    const int n_edges = in_sizes[4];

    cudaMemsetAsync(out, 0, (size_t)out_size * sizeof(float));

    rgcn_wprep<<<(N_RELS * FEAT * FEAT + 255) / 256, 256>>>(W);

    // device-global addresses for the GEMM's B operand (taken host-side via symbol)
    __nv_bfloat16* wthi_p = nullptr;
    __nv_bfloat16* wtlo_p = nullptr;
    cudaGetSymbolAddress((void**)&wthi_p, g_WT_hi);
    cudaGetSymbolAddress((void**)&wtlo_p, g_WT_lo);

    dim3 ggrid(N_RELS, (n_nodes + 127) / 128);
    rgcn_gemm_mma<<<ggrid, 256>>>(h, wthi_p, wtlo_p, n_nodes);

    rgcn_gate<<<((size_t)n_nodes * 32 + 255) / 256, 256>>>(h, gw, n_nodes);
    rgcn_edge<<<((size_t)n_edges * 32 + 255) / 256, 256>>>(src, dst, rel, norm, out, n_edges);

    int n4 = out_size / 4;
    rgcn_relu<<<(n4 + 255) / 256, 256>>>((float4*)out, n4);
}

// round 13
// speedup vs baseline: 1.6729x; 1.1067x over previous
#include <cuda_runtime.h>
#include <cuda_bf16.h>
#include <math.h>
#include <stdint.h>

#define FEAT      128
#define N_RELS    8
#define MAX_NODES 100000
#define BK        32
#define ASTRIDE   40            // bf16 elems per smem row (32 + 8 pad -> 80B)

// ---------------------------------------------------------------------------
// Scratch (__device__ globals: allocation-free rule)
// ---------------------------------------------------------------------------
__device__ float g_h_all[(size_t)MAX_NODES * N_RELS * FEAT];  // [n][r][f]
__device__ float g_gate [(size_t)MAX_NODES * N_RELS];
__device__ __align__(16) __nv_bfloat16 g_WT_hi[N_RELS * FEAT * FEAT]; // [r][f][d]
__device__ __align__(16) __nv_bfloat16 g_WT_lo[N_RELS * FEAT * FEAT];

// mma.sync bf16 (legal on plain sm_103 target; no tcgen05 anywhere)
#define MMA_BF16(d, a, b) \
    asm volatile("mma.sync.aligned.m16n8k16.row.col.f32.bf16.bf16.f32 " \
        "{%0,%1,%2,%3}, {%4,%5,%6,%7}, {%8,%9}, {%0,%1,%2,%3};" \
        : "+f"((d)[0]), "+f"((d)[1]), "+f"((d)[2]), "+f"((d)[3]) \
        : "r"((a)[0]), "r"((a)[1]), "r"((a)[2]), "r"((a)[3]), \
          "r"((b)[0]), "r"((b)[1]))

// ---------------------------------------------------------------------------
// W prep: transpose + bf16 hi/lo split.  out[r][f][d] from W[r][d][f]
// ---------------------------------------------------------------------------
__global__ void rgcn_wprep(const float* __restrict__ W) {
    int idx = blockIdx.x * blockDim.x + threadIdx.x;
    if (idx >= N_RELS * FEAT * FEAT) return;
    int d = idx & 127, f = (idx >> 7) & 127, r = idx >> 14;
    float w = W[((size_t)r * FEAT + d) * FEAT + f];
    __nv_bfloat16 hi = __float2bfloat16(w);
    float lo = w - __bfloat162float(hi);
    g_WT_hi[idx] = hi;
    g_WT_lo[idx] = __float2bfloat16(lo);
}

// ---------------------------------------------------------------------------
// Tensor GEMM (3xBF16): h_all[m][r][f] = h[m][:] @ W[r][:][f]
// CTA: 128 nodes x 128 feats for one rel. 256 thr = 8 warps (4m x 2n),
// warp tile 32x64, mma m16n8k16, K chunked by 32.
// ---------------------------------------------------------------------------
__global__ __launch_bounds__(256) void rgcn_gemm_mma(const float* __restrict__ h,
                                                     const __nv_bfloat16* __restrict__ WThi,
                                                     const __nv_bfloat16* __restrict__ WTlo,
                                                     int n_nodes)
{
    __shared__ __align__(16) __nv_bfloat16 sAhi[128 * ASTRIDE];
    __shared__ __align__(16) __nv_bfloat16 sAlo[128 * ASTRIDE];
    __shared__ __align__(16) __nv_bfloat16 sBhi[128 * ASTRIDE];
    __shared__ __align__(16) __nv_bfloat16 sBlo[128 * ASTRIDE];

    const int tid  = threadIdx.x;
    const int lane = tid & 31;
    const int warp = tid >> 5;
    const int wm   = (warp & 3) * 32;   // warp m offset (4 warps along M)
    const int wn   = (warp >> 2) * 64;  // warp n offset (2 warps along N)
    const int g    = lane >> 2;         // 0..7
    const int tg   = lane & 3;          // 0..3

    const int r     = blockIdx.x;       // rel fast -> 8 CTAs share A via L2
    const int mBase = blockIdx.y * 128;

    const int ldRow = tid >> 2;         // 0..63
    const int ldCol = (tid & 3) * 8;    // 0,8,16,24

    float acc[2][8][4] = {};

    for (int c = 0; c < 4; c++) {
        // ---- gmem fetch (overlaps previous chunk's MMAs) ----
        float4 av[2][2];
        uint4  bh[2], bl[2];
#pragma unroll
        for (int half = 0; half < 2; half++) {
            const int row = half * 64 + ldRow;
            const int m   = mBase + row;
            av[half][0] = make_float4(0.f, 0.f, 0.f, 0.f);
            av[half][1] = make_float4(0.f, 0.f, 0.f, 0.f);
            if (m < n_nodes) {
                const float* p = h + (size_t)m * FEAT + c * BK + ldCol;
                av[half][0] = *(const float4*)p;
                av[half][1] = *(const float4*)(p + 4);
            }
            const size_t bi = ((size_t)(r * 128 + row)) * 128 + c * BK + ldCol;
            bh[half] = *(const uint4*)(WThi + bi);
            bl[half] = *(const uint4*)(WTlo + bi);
        }

        __syncthreads();   // previous chunk's fragment reads are done

        // ---- split + stage into smem ----
#pragma unroll
        for (int half = 0; half < 2; half++) {
            const int row = half * 64 + ldRow;
            __nv_bfloat16 hi8[8], lo8[8];
            const float* fv = (const float*)&av[half][0];
#pragma unroll
            for (int i = 0; i < 8; i++) {
                float x = fv[i];
                __nv_bfloat16 hb = __float2bfloat16(x);
                hi8[i] = hb;
                lo8[i] = __float2bfloat16(x - __bfloat162float(hb));
            }
            *(uint4*)&sAhi[row * ASTRIDE + ldCol] = *(const uint4*)hi8;
            *(uint4*)&sAlo[row * ASTRIDE + ldCol] = *(const uint4*)lo8;
            *(uint4*)&sBhi[row * ASTRIDE + ldCol] = bh[half];
            *(uint4*)&sBlo[row * ASTRIDE + ldCol] = bl[half];
        }
        __syncthreads();

        // ---- MMA: 2 ksteps x 3 split-terms x (2m x 8n) ----
#pragma unroll
        for (int ks = 0; ks < 2; ks++) {
            const int kk = ks * 16 + tg * 2;
            uint32_t ahi[2][4], alo[2][4], bhi[8][2], blo[8][2];
#pragma unroll
            for (int mt = 0; mt < 2; mt++) {
                const int mr = wm + mt * 16 + g;
                ahi[mt][0] = *(const uint32_t*)&sAhi[mr * ASTRIDE + kk];
                ahi[mt][1] = *(const uint32_t*)&sAhi[(mr + 8) * ASTRIDE + kk];
                ahi[mt][2] = *(const uint32_t*)&sAhi[mr * ASTRIDE + kk + 8];
                ahi[mt][3] = *(const uint32_t*)&sAhi[(mr + 8) * ASTRIDE + kk + 8];
                alo[mt][0] = *(const uint32_t*)&sAlo[mr * ASTRIDE + kk];
                alo[mt][1] = *(const uint32_t*)&sAlo[(mr + 8) * ASTRIDE + kk];
                alo[mt][2] = *(const uint32_t*)&sAlo[mr * ASTRIDE + kk + 8];
                alo[mt][3] = *(const uint32_t*)&sAlo[(mr + 8) * ASTRIDE + kk + 8];
            }
#pragma unroll
            for (int nt = 0; nt < 8; nt++) {
                const int nr = wn + nt * 8 + g;
                bhi[nt][0] = *(const uint32_t*)&sBhi[nr * ASTRIDE + kk];
                bhi[nt][1] = *(const uint32_t*)&sBhi[nr * ASTRIDE + kk + 8];
                blo[nt][0] = *(const uint32_t*)&sBlo[nr * ASTRIDE + kk];
                blo[nt][1] = *(const uint32_t*)&sBlo[nr * ASTRIDE + kk + 8];
            }
#pragma unroll
            for (int mt = 0; mt < 2; mt++)
#pragma unroll
                for (int nt = 0; nt < 8; nt++) {
                    MMA_BF16(acc[mt][nt], ahi[mt], bhi[nt]);
                    MMA_BF16(acc[mt][nt], ahi[mt], blo[nt]);
                    MMA_BF16(acc[mt][nt], alo[mt], bhi[nt]);
                }
        }
    }

    // ---- epilogue: c-frag rows (g, g+8), cols tg*2..+1 per n-tile ----
#pragma unroll
    for (int mt = 0; mt < 2; mt++) {
#pragma unroll
        for (int ro = 0; ro < 2; ro++) {
            const int m = mBase + wm + mt * 16 + g + ro * 8;
            if (m < n_nodes) {
                float* dstp = g_h_all + ((size_t)m * N_RELS + r) * FEAT;
#pragma unroll
                for (int nt = 0; nt < 8; nt++) {
                    float2 v;
                    v.x = acc[mt][nt][ro * 2 + 0];
                    v.y = acc[mt][nt][ro * 2 + 1];
                    *(float2*)(dstp + wn + nt * 8 + tg * 2) = v;
                }
            }
        }
    }
}

// ---------------------------------------------------------------------------
// Gate GEMV (warp per node)
// ---------------------------------------------------------------------------
__global__ __launch_bounds__(256) void rgcn_gate(const float* __restrict__ h,
                                                 const float* __restrict__ gw,
                                                 int n_nodes)
{
    __shared__ float sgw[N_RELS][FEAT];
    for (int i = threadIdx.x; i < N_RELS * FEAT; i += blockDim.x)
        sgw[i / FEAT][i % FEAT] = gw[i];
    __syncthreads();

    int warp = (blockIdx.x * blockDim.x + threadIdx.x) >> 5;
    int lane = threadIdx.x & 31;
    if (warp >= n_nodes) return;

    float4 hv = *(const float4*)(h + (size_t)warp * FEAT + lane * 4);
#pragma unroll
    for (int r = 0; r < N_RELS; r++) {
        float4 wv = *(const float4*)&sgw[r][lane * 4];
        float d = hv.x * wv.x + hv.y * wv.y + hv.z * wv.z + hv.w * wv.w;
#pragma unroll
        for (int off = 16; off; off >>= 1)
            d += __shfl_xor_sync(0xffffffffu, d, off);
        if (lane == 0) g_gate[(size_t)warp * N_RELS + r] = d;
    }
}

// ---------------------------------------------------------------------------
// Edge gather/scatter (warp per edge). One red.global.add.v4.f32 per lane
// (4x fewer reduction ops than scalar atomicAdd).
// ---------------------------------------------------------------------------
__global__ __launch_bounds__(256) void rgcn_edge(const int* __restrict__ src,
                                                 const int* __restrict__ dst,
                                                 const int* __restrict__ rel,
                                                 const float* __restrict__ norm,
                                                 float* __restrict__ out,
                                                 int n_edges)
{
    int warp = (blockIdx.x * blockDim.x + threadIdx.x) >> 5;
    int lane = threadIdx.x & 31;
    if (warp >= n_edges) return;

    int s = src[warp], d = dst[warp], r = rel[warp];
    float gv    = g_gate[(size_t)s * N_RELS + r];
    float scale = norm[warp] / (1.0f + __expf(-gv));

    const float4* hp = (const float4*)(g_h_all + ((size_t)s * N_RELS + r) * FEAT);
    float4 v = hp[lane];

    float* o = out + (size_t)d * FEAT + lane * 4;   // 16B aligned
    asm volatile("red.global.add.v4.f32 [%0], {%1, %2, %3, %4};"
                 :: "l"(o), "f"(v.x * scale), "f"(v.y * scale),
                    "f"(v.z * scale), "f"(v.w * scale)
                 : "memory");
}

__global__ void rgcn_relu(float4* out, int n4)
{
    int i = blockIdx.x * blockDim.x + threadIdx.x;
    if (i < n4) {
        float4 v = out[i];
        v.x = fmaxf(v.x, 0.f); v.y = fmaxf(v.y, 0.f);
        v.z = fmaxf(v.z, 0.f); v.w = fmaxf(v.w, 0.f);
        out[i] = v;
    }
}

extern "C" void kernel_launch(void* const* d_in, const int* in_sizes, int n_in,
                              void* d_out, int out_size)
{
    const float* h    = (const float*)d_in[0];
    const float* W    = (const float*)d_in[1];
    const float* gw   = (const float*)d_in[2];
    const float* norm = (const float*)d_in[3];
    const int*   src  = (const int*)  d_in[4];
    const int*   dst  = (const int*)  d_in[5];
    const int*   rel  = (const int*)  d_in[6];
    float* out = (float*)d_out;

    const int n_nodes = in_sizes[0] / FEAT;
    const int n_edges = in_sizes[4];

    cudaMemsetAsync(out, 0, (size_t)out_size * sizeof(float));

    rgcn_wprep<<<(N_RELS * FEAT * FEAT + 255) / 256, 256>>>(W);

    __nv_bfloat16* wthi_p = nullptr;
    __nv_bfloat16* wtlo_p = nullptr;
    cudaGetSymbolAddress((void**)&wthi_p, g_WT_hi);
    cudaGetSymbolAddress((void**)&wtlo_p, g_WT_lo);

    dim3 ggrid(N_RELS, (n_nodes + 127) / 128);
    rgcn_gemm_mma<<<ggrid, 256>>>(h, wthi_p, wtlo_p, n_nodes);

    rgcn_gate<<<((size_t)n_nodes * 32 + 255) / 256, 256>>>(h, gw, n_nodes);
    rgcn_edge<<<((size_t)n_edges * 32 + 255) / 256, 256>>>(src, dst, rel, norm, out, n_edges);

    int n4 = out_size / 4;
    rgcn_relu<<<(n4 + 255) / 256, 256>>>((float4*)out, n4);
}